// round 7
// baseline (speedup 1.0000x reference)
#include <cuda_runtime.h>
#include <math.h>

#define NB      296              // 2 blocks per SM
#define NTHR    256              // 8 warps
#define NWARP   8
#define TOTW    (NB * NWARP)     // 2368 warps total

#define WSTRIDE 9472             // per-warp shared: hid 32x33 ull + wpk 32x4 ull
#define SM_TOTAL (2048 + NWARP * WSTRIDE)   // 77824 bytes dynamic

typedef unsigned long long ull;

// Per-block partials: [block][head][ s, acc[64] ]  (fixed softmax base = 0;
// per-head constant score offset cancels in A/S -> dropped entirely)
__device__ float g_part[NB][4][65];
__device__ unsigned g_done = 0;

// ---- packed f32x2 helpers (ptxas never auto-fuses FFMA2) --------------------
__device__ __forceinline__ ull pk2(float lo, float hi) {
    ull r; asm("mov.b64 %0,{%1,%2};" : "=l"(r) : "f"(lo), "f"(hi)); return r;
}
__device__ __forceinline__ void upk2(float& lo, float& hi, ull p) {
    asm("mov.b64 {%0,%1},%2;" : "=f"(lo), "=f"(hi) : "l"(p));
}
__device__ __forceinline__ ull fma2(ull a, ull b, ull c) {
    ull d; asm("fma.rn.f32x2 %0,%1,%2,%3;" : "=l"(d) : "l"(a), "l"(b), "l"(c)); return d;
}
__device__ __forceinline__ float tanh_ap(float x) {
    float y; asm("tanh.approx.f32 %0,%1;" : "=f"(y) : "f"(x)); return y;
}
__device__ __forceinline__ float ex2_ap(float x) {
    float y; asm("ex2.approx.f32 %0,%1;" : "=f"(y) : "f"(x)); return y;
}
// silu(x) = h + h*tanh(h) with h = x/2 (the 1/2 is pre-folded into W1/b1)
__device__ __forceinline__ ull silu2h(ull hpk) {
    float h0, h1; upk2(h0, h1, hpk);
    ull tpk = pk2(tanh_ap(h0), tanh_ap(h1));
    return fma2(hpk, tpk, hpk);
}

// -----------------------------------------------------------------------------
// One point per lane. Per 32-point warp-tile:
//   phase 1: lane computes its point's 64-dim hidden (packed pairs) streaming
//            constants from shared (uniform broadcasts), its 4 score dots,
//            w = ex2(score); stages hid pairs + duplicated w to shared.
//   phase 2: lane j accumulates acc[h][pair j] += w_p * hid_p[j] over 32 points.
// No shuffles, no divergence, 32 independent chains per warp.
// -----------------------------------------------------------------------------
__global__ void __launch_bounds__(NTHR, 2)
main_kernel(const float* __restrict__ rr,
            const float* __restrict__ ri,
            const float* __restrict__ W1,
            const float* __restrict__ b1,
            const float* __restrict__ W2,
            const float* __restrict__ b2,
            const float* __restrict__ query,
            const float* __restrict__ ipw,   // in_proj_w (192,64)
            const float* __restrict__ ipb,   // in_proj_b (192)
            const float* __restrict__ opw,   // out_proj_w (64,64)
            const float* __restrict__ opb,   // out_proj_b (64)
            float* __restrict__ out,
            int N)
{
    extern __shared__ char sm[];
    ull (*u_pk)[4]  = (ull(*)[4])(sm);               // [pair][head], 1024B
    ull (*cpk)[4]   = (ull(*)[4])(sm + 1024);        // [pair]{w1a,w1b,b1h,pad}

    const int tid  = threadIdx.x;
    const int lane = tid & 31;
    const int wid  = tid >> 5;

    ull (*whid)[33] = (ull(*)[33])(sm + 2048 + wid * WSTRIDE);          // [pair][point]
    ull (*wpk)[4]   = (ull(*)[4])(sm + 2048 + wid * WSTRIDE + 8448);    // [point][head]

    // prep scratch (aliases warp-0 tile region; done before main loop)
    float* qv        = (float*)(sm + 2048);
    float (*tt)[64]  = (float(*)[64])(sm + 2304);
    float (*sh_u)[64]= (float(*)[64])(sm + 3328);

    // scale = 1/sqrt(hd) * log2(e), folded into u so inner exp is bare ex2
    const float SC = 0.25f * 1.4426950408889634f;

    // ---- inline prep (every block redundantly; L2-resident) -----------------
    if (tid < 64) {
        float a = ipb[tid], a2 = 0.f;
        #pragma unroll 8
        for (int m = 0; m < 64; m += 2) {
            a  = fmaf(query[m],     ipw[tid * 64 + m],     a);
            a2 = fmaf(query[m + 1], ipw[tid * 64 + m + 1], a2);
        }
        qv[tid] = a + a2;
    }
    __syncthreads();
    {
        const int h = tid >> 6, j = tid & 63;
        float t = 0.f;
        #pragma unroll 8
        for (int d = 0; d < 16; d++)
            t = fmaf(qv[h * 16 + d], ipw[(64 + h * 16 + d) * 64 + j], t);
        tt[h][j] = t;
    }
    __syncthreads();
    {
        const int h = tid >> 6, j = tid & 63;
        float u = 0.f, u2 = 0.f;
        #pragma unroll 8
        for (int jj = 0; jj < 64; jj += 2) {
            u  = fmaf(tt[h][jj],     W2[jj * 64 + j],       u);
            u2 = fmaf(tt[h][jj + 1], W2[(jj + 1) * 64 + j], u2);
        }
        sh_u[h][j] = SC * (u + u2);
    }
    __syncthreads();
    if (tid < 128) {                              // pack u: [pair][head]
        const int pr = tid >> 2, h = tid & 3;
        u_pk[pr][h] = pk2(sh_u[h][2 * pr], sh_u[h][2 * pr + 1]);
    } else if (tid < 160) {                       // pack W1/b1 (0.5 pre-folded)
        const int pr = tid - 128;
        cpk[pr][0] = pk2(0.5f * W1[4 * pr],     0.5f * W1[4 * pr + 2]);
        cpk[pr][1] = pk2(0.5f * W1[4 * pr + 1], 0.5f * W1[4 * pr + 3]);
        cpk[pr][2] = pk2(0.5f * b1[2 * pr],     0.5f * b1[2 * pr + 1]);
        cpk[pr][3] = 0ull;
    }
    __syncthreads();

    // ---- streaming warp tiles -------------------------------------------------
    float s4[4] = {0.f, 0.f, 0.f, 0.f};
    ull acc[4]  = {0ull, 0ull, 0ull, 0ull};       // lane j owns dim pair j

    const int warp_gid = blockIdx.x * NWARP + wid;
    for (int base = warp_gid * 32; base < N; base += TOTW * 32) {
        const int p  = base + lane;
        const bool ok = (p < N);
        const int pc = ok ? p : (N - 1);
        const float r = __ldg(rr + pc);
        const float q = __ldg(ri + pc);
        const ull rpk = pk2(r, r), ipk = pk2(q, q);

        // phase 1: own point's hidden + scores
        ull part[4] = {0ull, 0ull, 0ull, 0ull};
        #pragma unroll 8
        for (int pr = 0; pr < 32; pr++) {
            const ulonglong2 c01 = *(const ulonglong2*)&cpk[pr][0];
            const ull b1h = cpk[pr][2];
            ull hh = fma2(ipk, c01.y, fma2(rpk, c01.x, b1h));
            const ull hid = silu2h(hh);
            whid[pr][lane] = hid;                                // STS.64, cf-free
            const ulonglong2 u01 = *(const ulonglong2*)&u_pk[pr][0];
            const ulonglong2 u23 = *(const ulonglong2*)&u_pk[pr][2];
            part[0] = fma2(u01.x, hid, part[0]);
            part[1] = fma2(u01.y, hid, part[1]);
            part[2] = fma2(u23.x, hid, part[2]);
            part[3] = fma2(u23.y, hid, part[3]);
        }
        #pragma unroll
        for (int h = 0; h < 4; h++) {
            float a, b; upk2(a, b, part[h]);
            const float w = ok ? ex2_ap(a + b) : 0.f;
            s4[h] += w;
            wpk[lane][h] = pk2(w, w);                            // duplicated
        }
        __syncwarp();

        // phase 2: accumulate over the tile's 32 points (dim pair = lane)
        #pragma unroll 8
        for (int pp = 0; pp < 32; pp++) {
            const ulonglong2 w01 = *(const ulonglong2*)&wpk[pp][0];  // broadcast
            const ulonglong2 w23 = *(const ulonglong2*)&wpk[pp][2];
            const ull hidv = whid[lane][pp];                         // 2-way max
            acc[0] = fma2(w01.x, hidv, acc[0]);
            acc[1] = fma2(w01.y, hidv, acc[1]);
            acc[2] = fma2(w23.x, hidv, acc[2]);
            acc[3] = fma2(w23.y, hidv, acc[3]);
        }
        __syncwarp();
    }

    // ---- block combine ---------------------------------------------------------
    __syncthreads();                              // all tiles done; re-alias smem
    float (*accF)[4][64] = (float(*)[4][64])(sm + 2048);
    float (*sF)[4]       = (float(*)[4])(sm + 2048 + 8192);

    #pragma unroll
    for (int off = 1; off <= 16; off <<= 1)
        #pragma unroll
        for (int h = 0; h < 4; h++)
            s4[h] += __shfl_xor_sync(0xffffffffu, s4[h], off);
    #pragma unroll
    for (int h = 0; h < 4; h++) {
        float a, b; upk2(a, b, acc[h]);
        accF[wid][h][2 * lane]     = a;
        accF[wid][h][2 * lane + 1] = b;
    }
    if (lane == 0)
        #pragma unroll
        for (int h = 0; h < 4; h++) sF[wid][h] = s4[h];
    __syncthreads();

    {
        const int h = tid >> 6, j = tid & 63;
        float A = 0.f;
        #pragma unroll
        for (int w = 0; w < NWARP; w++) A += accF[w][h][j];
        g_part[blockIdx.x][h][1 + j] = A;
        if (j == 0) {
            float S = 0.f;
            #pragma unroll
            for (int w = 0; w < NWARP; w++) S += sF[w][h];
            g_part[blockIdx.x][h][0] = S;
        }
    }

    // ---- last block: combine partials + output projections ---------------------
    __threadfence();
    __shared__ bool is_last;
    if (tid == 0) is_last = (atomicAdd(&g_done, 1) == NB - 1);
    __syncthreads();
    if (!is_last) return;
    if (tid == 0) g_done = 0;                     // reset for next graph replay

    float (*sh_p)[64]  = (float(*)[64])(sm + 10368);
    float (*sh_hb)[64] = (float(*)[64])(sm + 11392);
    float* sh_pool     = (float*)(sm + 12416);
    float* sh_S        = (float*)(sm + 12672);

    const int h = tid >> 6, j = tid & 63;

    if (tid >= 252) {
        const int hh = tid - 252;
        float S = 0.f;
        #pragma unroll 4
        for (int b = 0; b < NB; b++) S += __ldg(&g_part[b][hh][0]);
        sh_S[hh] = S;
    }
    float A = 0.f;
    #pragma unroll 4
    for (int b = 0; b < NB; b++) A += __ldg(&g_part[b][h][1 + j]);
    __syncthreads();
    sh_p[h][j] = A / sh_S[h];                     // E[hidden] under attn, head h
    __syncthreads();

    {
        float hb = b2[j];
        #pragma unroll 8
        for (int m = 0; m < 64; m++) hb = fmaf(W2[j * 64 + m], sh_p[h][m], hb);
        sh_hb[h][j] = hb;
    }
    __syncthreads();

    if (tid < 64) {
        const int e = tid, hh = tid >> 4;
        float pl = ipb[128 + e];
        #pragma unroll 8
        for (int jj = 0; jj < 64; jj++)
            pl = fmaf(ipw[(128 + e) * 64 + jj], sh_hb[hh][jj], pl);
        sh_pool[e] = pl;
    }
    __syncthreads();

    if (tid < 64) {
        float o = opb[tid];
        #pragma unroll 8
        for (int e = 0; e < 64; e++) o = fmaf(opw[tid * 64 + e], sh_pool[e], o);
        out[tid] = o;
    }
}

// -----------------------------------------------------------------------------
extern "C" void kernel_launch(void* const* d_in, const int* in_sizes, int n_in,
                              void* d_out, int out_size)
{
    const float* rr    = (const float*)d_in[0];   // rho_real (1024*1024)
    const float* ri    = (const float*)d_in[1];   // rho_imag
    // d_in[2..5]: l_A, l_B, Z_A, Z_B — unused by the reference math
    const float* W1    = (const float*)d_in[6];   // (64,2)
    const float* b1    = (const float*)d_in[7];   // (64)
    const float* W2    = (const float*)d_in[8];   // (64,64)
    const float* b2    = (const float*)d_in[9];   // (64)
    const float* query = (const float*)d_in[10];  // (1,64)
    const float* ipw   = (const float*)d_in[11];  // (192,64)
    const float* ipb   = (const float*)d_in[12];  // (192)
    const float* opw   = (const float*)d_in[13];  // (64,64)
    const float* opb   = (const float*)d_in[14];  // (64)
    const int N = in_sizes[0];

    cudaFuncSetAttribute(main_kernel,
                         cudaFuncAttributeMaxDynamicSharedMemorySize, SM_TOTAL);
    main_kernel<<<NB, NTHR, SM_TOTAL>>>(rr, ri, W1, b1, W2, b2, query, ipw, ipb,
                                        opw, opb, (float*)d_out, N);
}

// round 8
// speedup vs baseline: 1.5002x; 1.5002x over previous
#include <cuda_runtime.h>
#include <math.h>

#define NB      148              // one block per SM, single wave
#define NTHR    512              // 16 warps, 4/SMSP; 128 regs/thread budget
#define GPB     (NTHR / 8)       // 64 groups per block
#define NGROUPS (NB * GPB)       // 9472
#define NWARP   (NTHR / 32)      // 16

typedef unsigned long long ull;

// Per-block partials: [block][head][ s, acc[64] ]  (fixed softmax base = 0;
// per-head constant score offset cancels in A/S -> dropped entirely)
__device__ float g_part[NB][4][65];
__device__ unsigned g_done = 0;

// ---- packed f32x2 helpers (ptxas never auto-fuses FFMA2) --------------------
__device__ __forceinline__ ull pk2(float lo, float hi) {
    ull r; asm("mov.b64 %0,{%1,%2};" : "=l"(r) : "f"(lo), "f"(hi)); return r;
}
__device__ __forceinline__ void upk2(float& lo, float& hi, ull p) {
    asm("mov.b64 {%0,%1},%2;" : "=f"(lo), "=f"(hi) : "l"(p));
}
__device__ __forceinline__ ull fma2(ull a, ull b, ull c) {
    ull d; asm("fma.rn.f32x2 %0,%1,%2,%3;" : "=l"(d) : "l"(a), "l"(b), "l"(c)); return d;
}
__device__ __forceinline__ float tanh_ap(float x) {
    float y; asm("tanh.approx.f32 %0,%1;" : "=f"(y) : "f"(x)); return y;
}
__device__ __forceinline__ float ex2_ap(float x) {
    float y; asm("ex2.approx.f32 %0,%1;" : "=f"(y) : "f"(x)); return y;
}
// silu(x) = h + h*tanh(h) with h = x/2 (the 1/2 is pre-folded into W1/b1)
__device__ __forceinline__ ull silu2h(ull hpk) {
    float h0, h1; upk2(h0, h1, hpk);
    ull tpk = pk2(tanh_ap(h0), tanh_ap(h1));
    return fma2(hpk, tpk, hpk);
}

// -----------------------------------------------------------------------------
// Single fused kernel: inline prep -> branch-free streaming exp-accumulate
// (1 point per group-iter, next point prefetched) -> block partial -> last
// block does final combine + projections.  8 lanes per point.
// -----------------------------------------------------------------------------
__global__ void __launch_bounds__(NTHR, 1)
main_kernel(const float* __restrict__ rr,
            const float* __restrict__ ri,
            const float* __restrict__ W1,
            const float* __restrict__ b1,
            const float* __restrict__ W2,
            const float* __restrict__ b2,
            const float* __restrict__ query,
            const float* __restrict__ ipw,   // in_proj_w (192,64)
            const float* __restrict__ ipb,   // in_proj_b (192)
            const float* __restrict__ opw,   // out_proj_w (64,64)
            const float* __restrict__ opb,   // out_proj_b (64)
            float* __restrict__ out,
            int N)
{
    __shared__ float qv[64];
    __shared__ float tt[4][64];
    __shared__ float sh_u[4][64];
    __shared__ float sh_acc[NWARP][4][64];
    __shared__ float sh_s[NWARP][4];

    const int tid  = threadIdx.x;
    const int lane = tid & 31;
    const int sub  = tid & 7;
    const unsigned gmask = 0xFFu << (lane & 24);

    // scale = 1/sqrt(hd) * log2(e), folded into u so inner exp is bare ex2
    const float SC = 0.25f * 1.4426950408889634f;

    // ---- inline prep (every block redundantly; ~25K FMA, L2-resident) ------
    if (tid < 64) {
        float a = ipb[tid], a2 = 0.f;
        #pragma unroll 8
        for (int m = 0; m < 64; m += 2) {
            a  = fmaf(query[m],     ipw[tid * 64 + m],     a);
            a2 = fmaf(query[m + 1], ipw[tid * 64 + m + 1], a2);
        }
        qv[tid] = a + a2;
    }
    __syncthreads();
    if (tid < 256) {
        const int h = tid >> 6, j = tid & 63;
        float t = 0.f;
        #pragma unroll 8
        for (int d = 0; d < 16; d++)
            t = fmaf(qv[h * 16 + d], ipw[(64 + h * 16 + d) * 64 + j], t);
        tt[h][j] = t;
    }
    __syncthreads();
    if (tid < 256) {
        const int h = tid >> 6, j = tid & 63;
        float u = 0.f, u2 = 0.f;
        #pragma unroll 8
        for (int jj = 0; jj < 64; jj += 2) {
            u  = fmaf(tt[h][jj],     W2[jj * 64 + j],       u);
            u2 = fmaf(tt[h][jj + 1], W2[(jj + 1) * 64 + j], u2);
        }
        sh_u[h][j] = SC * (u + u2);
    }
    __syncthreads();

    // ---- per-lane packed constants (0.5 silu factor pre-folded) -------------
    const int j0 = sub * 8;
    ull w1ap[4], w1bp[4], b1p[4], u4p[4][4];
    #pragma unroll
    for (int k = 0; k < 4; k++) {
        const int j = j0 + 2 * k;
        w1ap[k] = pk2(0.5f * W1[2 * j],     0.5f * W1[2 * j + 2]);
        w1bp[k] = pk2(0.5f * W1[2 * j + 1], 0.5f * W1[2 * j + 3]);
        b1p[k]  = pk2(0.5f * b1[j], 0.5f * b1[j + 1]);
        #pragma unroll
        for (int h = 0; h < 4; h++) u4p[h][k] = pk2(sh_u[h][j], sh_u[h][j + 1]);
    }

    // ---- accumulators (fixed base: w = 2^sc, softmax shift-invariant) -------
    float s4[4] = {0.f, 0.f, 0.f, 0.f};
    ull accp[4][4];
    #pragma unroll
    for (int h = 0; h < 4; h++)
        #pragma unroll
        for (int k = 0; k < 4; k++) accp[h][k] = 0ull;

    // ---- branch-free streaming loop: 1 point/iter, next prefetched -----------
    const int gid = blockIdx.x * GPB + (tid >> 3);
    int p = gid;
    {
        const int p0 = (p < N) ? p : 0;
        float r  = __ldg(rr + p0);
        float im = __ldg(ri + p0);
        while (p < N) {
            const int pn = p + NGROUPS;
            const int pc = (pn < N) ? pn : p;      // clamped prefetch index
            const float r_n  = __ldg(rr + pc);
            const float im_n = __ldg(ri + pc);

            const ull rpk = pk2(r, r);
            const ull ipk = pk2(im, im);
            ull hid[4];
            ull partp[4] = {0ull, 0ull, 0ull, 0ull};
            #pragma unroll
            for (int k = 0; k < 4; k++) {
                ull hh = fma2(rpk, w1ap[k], b1p[k]);
                hh = fma2(ipk, w1bp[k], hh);
                hid[k] = silu2h(hh);
                #pragma unroll
                for (int h = 0; h < 4; h++)
                    partp[h] = fma2(u4p[h][k], hid[k], partp[h]);
            }
            float sc[4];
            #pragma unroll
            for (int h = 0; h < 4; h++) { float a, b; upk2(a, b, partp[h]); sc[h] = a + b; }

            // butterfly over the 8 group lanes (group-scoped mask: trip counts
            // differ by 1 across groups in the same warp)
            #pragma unroll
            for (int off = 1; off < 8; off <<= 1) {
                #pragma unroll
                for (int h = 0; h < 4; h++)
                    sc[h] += __shfl_xor_sync(gmask, sc[h], off);
            }

            #pragma unroll
            for (int h = 0; h < 4; h++) {
                const float w = ex2_ap(sc[h]);
                s4[h] += w;
                const ull wpk = pk2(w, w);
                #pragma unroll
                for (int k = 0; k < 4; k++)
                    accp[h][k] = fma2(wpk, hid[k], accp[h][k]);
            }

            p = pn; r = r_n; im = im_n;
        }
    }

    // ---- combine 4 groups of this warp (plain sums) ---------------------------
    #pragma unroll
    for (int off = 8; off <= 16; off <<= 1) {
        #pragma unroll
        for (int h = 0; h < 4; h++) {
            s4[h] += __shfl_xor_sync(0xffffffffu, s4[h], off);
            #pragma unroll
            for (int k = 0; k < 4; k++) {
                float a, b; upk2(a, b, accp[h][k]);
                a += __shfl_xor_sync(0xffffffffu, a, off);
                b += __shfl_xor_sync(0xffffffffu, b, off);
                accp[h][k] = pk2(a, b);
            }
        }
    }

    // ---- block combine via shared ---------------------------------------------
    const int wid = tid >> 5;
    if (lane < 8) {
        #pragma unroll
        for (int h = 0; h < 4; h++) {
            #pragma unroll
            for (int k = 0; k < 4; k++) {
                float a, b; upk2(a, b, accp[h][k]);
                sh_acc[wid][h][lane * 8 + 2 * k]     = a;
                sh_acc[wid][h][lane * 8 + 2 * k + 1] = b;
            }
            if (lane == 0) sh_s[wid][h] = s4[h];
        }
    }
    __syncthreads();

    if (tid < 256) {
        const int h = tid >> 6;
        const int j = tid & 63;
        float A = 0.f;
        #pragma unroll
        for (int w = 0; w < NWARP; w++) A += sh_acc[w][h][j];
        g_part[blockIdx.x][h][1 + j] = A;
        if (j == 0) {
            float S = 0.f;
            #pragma unroll
            for (int w = 0; w < NWARP; w++) S += sh_s[w][h];
            g_part[blockIdx.x][h][0] = S;
        }
    }

    // ---- last block does the final combine + projections -----------------------
    __threadfence();
    __shared__ bool is_last;
    __shared__ float sh_p[4][64];
    __shared__ float sh_hbar[4][64];
    __shared__ float sh_pooled[64];
    __shared__ float sh_S[4];
    if (tid == 0) is_last = (atomicAdd(&g_done, 1) == NB - 1);
    __syncthreads();
    if (!is_last) return;
    if (tid == 0) g_done = 0;            // reset for next graph replay

    const int h = (tid >> 6) & 3;
    const int j = tid & 63;

    if (tid < 256) {
        float A = 0.f;
        #pragma unroll 4
        for (int b = 0; b < NB; b++) A += __ldg(&g_part[b][h][1 + j]);
        sh_hbar[h][j] = A;               // staging: raw acc sum
    } else if (tid < 260) {
        const int hh = tid - 256;
        float S = 0.f;
        #pragma unroll 4
        for (int b = 0; b < NB; b++) S += __ldg(&g_part[b][hh][0]);
        sh_S[hh] = S;
    }
    __syncthreads();
    if (tid < 256) sh_p[h][j] = sh_hbar[h][j] / sh_S[h];   // E[hidden] head h
    __syncthreads();

    if (tid < 256) {
        float hb = b2[j];
        #pragma unroll 8
        for (int m = 0; m < 64; m++) hb = fmaf(W2[j * 64 + m], sh_p[h][m], hb);
        sh_hbar[h][j] = hb;
    }
    __syncthreads();

    if (tid < 64) {
        const int e = tid, hh = tid >> 4;
        float pl = ipb[128 + e];
        #pragma unroll 8
        for (int jj = 0; jj < 64; jj++)
            pl = fmaf(ipw[(128 + e) * 64 + jj], sh_hbar[hh][jj], pl);
        sh_pooled[e] = pl;
    }
    __syncthreads();

    if (tid < 64) {
        float o = opb[tid];
        #pragma unroll 8
        for (int e = 0; e < 64; e++) o = fmaf(opw[tid * 64 + e], sh_pooled[e], o);
        out[tid] = o;
    }
}

// -----------------------------------------------------------------------------
extern "C" void kernel_launch(void* const* d_in, const int* in_sizes, int n_in,
                              void* d_out, int out_size)
{
    const float* rr    = (const float*)d_in[0];   // rho_real (1024*1024)
    const float* ri    = (const float*)d_in[1];   // rho_imag
    // d_in[2..5]: l_A, l_B, Z_A, Z_B — unused by the reference math
    const float* W1    = (const float*)d_in[6];   // (64,2)
    const float* b1    = (const float*)d_in[7];   // (64)
    const float* W2    = (const float*)d_in[8];   // (64,64)
    const float* b2    = (const float*)d_in[9];   // (64)
    const float* query = (const float*)d_in[10];  // (1,64)
    const float* ipw   = (const float*)d_in[11];  // (192,64)
    const float* ipb   = (const float*)d_in[12];  // (192)
    const float* opw   = (const float*)d_in[13];  // (64,64)
    const float* opb   = (const float*)d_in[14];  // (64)
    const int N = in_sizes[0];

    main_kernel<<<NB, NTHR>>>(rr, ri, W1, b1, W2, b2, query, ipw, ipb,
                              opw, opb, (float*)d_out, N);
}